// round 1
// baseline (speedup 1.0000x reference)
#include <cuda_runtime.h>

#define N_NODES 400000
#define N_EDGES 1600000
#define N_GRAPHS 10000
#define H 64
#define NODE_DIM 74
#define EDGE_DIM 13

// ---------------- device scratch (no allocation allowed) ----------------
__device__ float g_node[(size_t)N_NODES * H];   // projected node features
__device__ float g_h0[(size_t)N_EDGES * H];     // initial edge hidden state
__device__ float g_hA[(size_t)N_EDGES * H];     // ping-pong edge states
__device__ float g_hB[(size_t)N_EDGES * H];
__device__ float g_aggA[(size_t)N_NODES * H];   // ping-pong segment sums
__device__ float g_aggB[(size_t)N_NODES * H];
__device__ float g_gpool[(size_t)N_GRAPHS * H]; // graph pooled features
__device__ float g_Wc[EDGE_DIM * H];            // We @ Wi_bot (folded)
__device__ float g_bc[H];                       // bi + be @ Wi_bot

__device__ __forceinline__ float lrelu(float v) { return v > 0.f ? v : 0.01f * v; }

// ---------------- fold the edge-feature projection through Wi ----------------
// Wc[d][j] = sum_k We[d][k] * Wi[64+k][j];  bc[j] = bi[j] + sum_k be[k]*Wi[64+k][j]
__global__ void prep_kernel(const float* __restrict__ We, const float* __restrict__ be,
                            const float* __restrict__ Wi, const float* __restrict__ bi,
                            float* __restrict__ Wc, float* __restrict__ bc) {
    int tid = blockIdx.x * blockDim.x + threadIdx.x;
    if (tid < EDGE_DIM * H) {
        int d = tid >> 6, j = tid & 63;
        float s = 0.f;
        #pragma unroll 8
        for (int k = 0; k < H; k++) s += We[d * H + k] * Wi[(H + k) * H + j];
        Wc[tid] = s;
    }
    if (tid < H) {
        float s = bi[tid];
        #pragma unroll 8
        for (int k = 0; k < H; k++) s += be[k] * Wi[(H + k) * H + tid];
        bc[tid] = s;
    }
}

// ---------------- node projection: node = node_feats @ Wn + bn ----------------
// warp per node, features broadcast via shfl, W in smem (float2 column pairs)
__global__ __launch_bounds__(256) void node_proj_kernel(
    const float* __restrict__ nf, const float* __restrict__ Wn,
    const float* __restrict__ bn, float* __restrict__ node) {
    __shared__ float2 sW[NODE_DIM][32];
    __shared__ float sb[H];
    for (int idx = threadIdx.x; idx < NODE_DIM * 32; idx += 256) {
        int k = idx >> 5, j = idx & 31;
        sW[k][j] = make_float2(Wn[k * H + j], Wn[k * H + j + 32]);
    }
    if (threadIdx.x < H) sb[threadIdx.x] = bn[threadIdx.x];
    __syncthreads();
    int warp = threadIdx.x >> 5, lane = threadIdx.x & 31;
    int n = blockIdx.x * 8 + warp;
    const float* row = nf + (size_t)n * NODE_DIM;
    float f0 = row[lane];
    float f1 = (lane + 32 < NODE_DIM) ? row[lane + 32] : 0.f;
    float f2 = (lane + 64 < NODE_DIM) ? row[lane + 64] : 0.f;
    float a0 = sb[lane], a1 = sb[lane + 32];
    #pragma unroll
    for (int k = 0; k < NODE_DIM; k++) {
        float fk = __shfl_sync(0xffffffffu, (k < 32 ? f0 : (k < 64 ? f1 : f2)), k & 31);
        float2 w = sW[k][lane];
        a0 += fk * w.x; a1 += fk * w.y;
    }
    node[n * H + lane] = a0;
    node[n * H + lane + 32] = a1;
}

// ---------------- h0 = lrelu(node[src] @ Wi_top + ef @ Wc + bc); scatter into agg ----------------
__global__ __launch_bounds__(256) void h0_kernel(
    const float* __restrict__ node, const float* __restrict__ ef,
    const int* __restrict__ src, const int* __restrict__ dst,
    const float* __restrict__ Wi, const float* __restrict__ Wc,
    const float* __restrict__ bc, float* __restrict__ h0,
    float* __restrict__ agg_out) {
    __shared__ float2 sWt[H][32];
    __shared__ float2 sWc[EDGE_DIM][32];
    __shared__ float4 sM[8][H];
    __shared__ float4 sE[8][EDGE_DIM];
    __shared__ float sb[H];
    for (int idx = threadIdx.x; idx < H * 32; idx += 256) {
        int k = idx >> 5, j = idx & 31;
        sWt[k][j] = make_float2(Wi[k * H + j], Wi[k * H + j + 32]);
    }
    for (int idx = threadIdx.x; idx < EDGE_DIM * 32; idx += 256) {
        int k = idx >> 5, j = idx & 31;
        sWc[k][j] = make_float2(Wc[k * H + j], Wc[k * H + j + 32]);
    }
    if (threadIdx.x < H) sb[threadIdx.x] = bc[threadIdx.x];
    __syncthreads();
    int warp = threadIdx.x >> 5, lane = threadIdx.x & 31;
    int eb = (blockIdx.x * 8 + warp) * 4;
    float m0[4], m1[4], fe[4];
    #pragma unroll
    for (int i = 0; i < 4; i++) {
        int e = eb + i;
        int s = src[e];
        m0[i] = node[s * H + lane];
        m1[i] = node[s * H + lane + 32];
        fe[i] = (lane < EDGE_DIM) ? ef[e * EDGE_DIM + lane] : 0.f;
    }
    sM[warp][lane]      = make_float4(m0[0], m0[1], m0[2], m0[3]);
    sM[warp][lane + 32] = make_float4(m1[0], m1[1], m1[2], m1[3]);
    if (lane < EDGE_DIM) sE[warp][lane] = make_float4(fe[0], fe[1], fe[2], fe[3]);
    __syncwarp();
    float a0[4], a1[4];
    #pragma unroll
    for (int i = 0; i < 4; i++) { a0[i] = sb[lane]; a1[i] = sb[lane + 32]; }
    #pragma unroll
    for (int k = 0; k < H; k++) {
        float4 mk = sM[warp][k];
        float2 w = sWt[k][lane];
        a0[0] += mk.x * w.x; a0[1] += mk.y * w.x; a0[2] += mk.z * w.x; a0[3] += mk.w * w.x;
        a1[0] += mk.x * w.y; a1[1] += mk.y * w.y; a1[2] += mk.z * w.y; a1[3] += mk.w * w.y;
    }
    #pragma unroll
    for (int d = 0; d < EDGE_DIM; d++) {
        float4 fd = sE[warp][d];
        float2 w = sWc[d][lane];
        a0[0] += fd.x * w.x; a0[1] += fd.y * w.x; a0[2] += fd.z * w.x; a0[3] += fd.w * w.x;
        a1[0] += fd.x * w.y; a1[1] += fd.y * w.y; a1[2] += fd.z * w.y; a1[3] += fd.w * w.y;
    }
    #pragma unroll
    for (int i = 0; i < 4; i++) {
        int e = eb + i;
        float v0 = lrelu(a0[i]);
        float v1 = lrelu(a1[i]);
        h0[e * H + lane] = v0;
        h0[e * H + lane + 32] = v1;
        int d = dst[e];
        atomicAdd(&agg_out[d * H + lane], v0);
        atomicAdd(&agg_out[d * H + lane + 32], v1);
    }
}

// ---------------- one DMPNN conv layer ----------------
// h_out[e] = lrelu(h0[e] + (agg_in[src[e]] - h_in[e^1]) @ W + b); scatter h_out into agg_out
__global__ __launch_bounds__(256) void conv_kernel(
    const float* __restrict__ W, const float* __restrict__ b,
    const int* __restrict__ src, const int* __restrict__ dst,
    const float* __restrict__ agg_in, const float* __restrict__ h_in,
    const float* __restrict__ h0, float* __restrict__ h_out,
    float* __restrict__ agg_out) {
    __shared__ float2 sW[H][32];
    __shared__ float4 sM[8][H];
    __shared__ float sb[H];
    for (int idx = threadIdx.x; idx < H * 32; idx += 256) {
        int k = idx >> 5, j = idx & 31;
        sW[k][j] = make_float2(W[k * H + j], W[k * H + j + 32]);
    }
    if (threadIdx.x < H) sb[threadIdx.x] = b[threadIdx.x];
    __syncthreads();
    int warp = threadIdx.x >> 5, lane = threadIdx.x & 31;
    int eb = (blockIdx.x * 8 + warp) * 4;
    float m0[4], m1[4];
    #pragma unroll
    for (int i = 0; i < 4; i++) {
        int e = eb + i;
        int s = src[e];
        int r = e ^ 1;
        m0[i] = agg_in[s * H + lane]      - h_in[r * H + lane];
        m1[i] = agg_in[s * H + lane + 32] - h_in[r * H + lane + 32];
    }
    sM[warp][lane]      = make_float4(m0[0], m0[1], m0[2], m0[3]);
    sM[warp][lane + 32] = make_float4(m1[0], m1[1], m1[2], m1[3]);
    __syncwarp();
    float a0[4], a1[4];
    #pragma unroll
    for (int i = 0; i < 4; i++) { a0[i] = sb[lane]; a1[i] = sb[lane + 32]; }
    #pragma unroll
    for (int k = 0; k < H; k++) {
        float4 mk = sM[warp][k];
        float2 w = sW[k][lane];
        a0[0] += mk.x * w.x; a0[1] += mk.y * w.x; a0[2] += mk.z * w.x; a0[3] += mk.w * w.x;
        a1[0] += mk.x * w.y; a1[1] += mk.y * w.y; a1[2] += mk.z * w.y; a1[3] += mk.w * w.y;
    }
    #pragma unroll
    for (int i = 0; i < 4; i++) {
        int e = eb + i;
        float v0 = lrelu(h0[e * H + lane]      + a0[i]);
        float v1 = lrelu(h0[e * H + lane + 32] + a1[i]);
        h_out[e * H + lane] = v0;
        h_out[e * H + lane + 32] = v1;
        int d = dst[e];
        atomicAdd(&agg_out[d * H + lane], v0);
        atomicAdd(&agg_out[d * H + lane + 32], v1);
    }
}

// ---------------- node readout + fused graph pooling ----------------
// node_h = lrelu([node, agg] @ Wa + ba); gpool[gid[n]] += node_h
__global__ __launch_bounds__(256) void readout_kernel(
    const float* __restrict__ node, const float* __restrict__ agg,
    const float* __restrict__ Wa, const float* __restrict__ ba,
    const int* __restrict__ gid, float* __restrict__ gpool) {
    __shared__ float2 sW[2 * H][32];   // 32 KB
    __shared__ float4 sM[8][H];
    __shared__ float sb[H];
    for (int idx = threadIdx.x; idx < 2 * H * 32; idx += 256) {
        int k = idx >> 5, j = idx & 31;
        sW[k][j] = make_float2(Wa[k * H + j], Wa[k * H + j + 32]);
    }
    if (threadIdx.x < H) sb[threadIdx.x] = ba[threadIdx.x];
    __syncthreads();
    int warp = threadIdx.x >> 5, lane = threadIdx.x & 31;
    int nb = (blockIdx.x * 8 + warp) * 4;
    float a0[4], a1[4];
    #pragma unroll
    for (int i = 0; i < 4; i++) { a0[i] = sb[lane]; a1[i] = sb[lane + 32]; }
    // stage 0: node features through Wa[0:64]
    {
        float m0[4], m1[4];
        #pragma unroll
        for (int i = 0; i < 4; i++) {
            int n = nb + i;
            m0[i] = node[n * H + lane];
            m1[i] = node[n * H + lane + 32];
        }
        sM[warp][lane]      = make_float4(m0[0], m0[1], m0[2], m0[3]);
        sM[warp][lane + 32] = make_float4(m1[0], m1[1], m1[2], m1[3]);
        __syncwarp();
        #pragma unroll
        for (int k = 0; k < H; k++) {
            float4 mk = sM[warp][k];
            float2 w = sW[k][lane];
            a0[0] += mk.x * w.x; a0[1] += mk.y * w.x; a0[2] += mk.z * w.x; a0[3] += mk.w * w.x;
            a1[0] += mk.x * w.y; a1[1] += mk.y * w.y; a1[2] += mk.z * w.y; a1[3] += mk.w * w.y;
        }
        __syncwarp();
    }
    // stage 1: aggregated edge states through Wa[64:128]
    {
        float m0[4], m1[4];
        #pragma unroll
        for (int i = 0; i < 4; i++) {
            int n = nb + i;
            m0[i] = agg[n * H + lane];
            m1[i] = agg[n * H + lane + 32];
        }
        sM[warp][lane]      = make_float4(m0[0], m0[1], m0[2], m0[3]);
        sM[warp][lane + 32] = make_float4(m1[0], m1[1], m1[2], m1[3]);
        __syncwarp();
        #pragma unroll
        for (int k = 0; k < H; k++) {
            float4 mk = sM[warp][k];
            float2 w = sW[H + k][lane];
            a0[0] += mk.x * w.x; a0[1] += mk.y * w.x; a0[2] += mk.z * w.x; a0[3] += mk.w * w.x;
            a1[0] += mk.x * w.y; a1[1] += mk.y * w.y; a1[2] += mk.z * w.y; a1[3] += mk.w * w.y;
        }
    }
    #pragma unroll
    for (int i = 0; i < 4; i++) {
        int n = nb + i;
        float v0 = lrelu(a0[i]);
        float v1 = lrelu(a1[i]);
        int g = gid[n];
        atomicAdd(&gpool[g * H + lane], v0);
        atomicAdd(&gpool[g * H + lane + 32], v1);
    }
}

// ---------------- head: out = lrelu(g @ W1 + b1) @ W2 + b2 ----------------
__global__ __launch_bounds__(256) void head_kernel(
    const float* __restrict__ g, const float* __restrict__ W1,
    const float* __restrict__ b1, const float* __restrict__ W2,
    const float* __restrict__ b2, float* __restrict__ out) {
    __shared__ float2 sW[H][32];
    __shared__ float sb[H];
    __shared__ float sW2[H];
    for (int idx = threadIdx.x; idx < H * 32; idx += 256) {
        int k = idx >> 5, j = idx & 31;
        sW[k][j] = make_float2(W1[k * H + j], W1[k * H + j + 32]);
    }
    if (threadIdx.x < H) { sb[threadIdx.x] = b1[threadIdx.x]; sW2[threadIdx.x] = W2[threadIdx.x]; }
    __syncthreads();
    int warp = threadIdx.x >> 5, lane = threadIdx.x & 31;
    int gi = blockIdx.x * 8 + warp;
    const float* row = g + gi * H;
    float f0 = row[lane], f1 = row[lane + 32];
    float a0 = sb[lane], a1 = sb[lane + 32];
    #pragma unroll
    for (int k = 0; k < H; k++) {
        float fk = __shfl_sync(0xffffffffu, (k < 32 ? f0 : f1), k & 31);
        float2 w = sW[k][lane];
        a0 += fk * w.x; a1 += fk * w.y;
    }
    a0 = lrelu(a0); a1 = lrelu(a1);
    float p = a0 * sW2[lane] + a1 * sW2[lane + 32];
    #pragma unroll
    for (int o = 16; o; o >>= 1) p += __shfl_xor_sync(0xffffffffu, p, o);
    if (lane == 0) out[gi] = p + b2[0];
}

// ---------------- launch ----------------
extern "C" void kernel_launch(void* const* d_in, const int* in_sizes, int n_in,
                              void* d_out, int out_size) {
    const float* node_feats = (const float*)d_in[0];
    const float* edge_feats = (const float*)d_in[1];
    const int*   src        = (const int*)d_in[2];
    const int*   dst        = (const int*)d_in[3];
    const int*   gid        = (const int*)d_in[4];
    const float* Wn = (const float*)d_in[5];
    const float* bn = (const float*)d_in[6];
    const float* We = (const float*)d_in[7];
    const float* be = (const float*)d_in[8];
    const float* Wi = (const float*)d_in[9];
    const float* bi = (const float*)d_in[10];
    const float* Wa = (const float*)d_in[11];
    const float* ba = (const float*)d_in[12];
    const float* Wl = (const float*)d_in[13];
    const float* bl = (const float*)d_in[14];
    const float* W1 = (const float*)d_in[15];
    const float* b1 = (const float*)d_in[16];
    const float* W2 = (const float*)d_in[17];
    const float* b2 = (const float*)d_in[18];
    float* out = (float*)d_out;

    float *p_node, *p_h0, *p_hA, *p_hB, *p_aggA, *p_aggB, *p_gpool, *p_Wc, *p_bc;
    cudaGetSymbolAddress((void**)&p_node, g_node);
    cudaGetSymbolAddress((void**)&p_h0, g_h0);
    cudaGetSymbolAddress((void**)&p_hA, g_hA);
    cudaGetSymbolAddress((void**)&p_hB, g_hB);
    cudaGetSymbolAddress((void**)&p_aggA, g_aggA);
    cudaGetSymbolAddress((void**)&p_aggB, g_aggB);
    cudaGetSymbolAddress((void**)&p_gpool, g_gpool);
    cudaGetSymbolAddress((void**)&p_Wc, g_Wc);
    cudaGetSymbolAddress((void**)&p_bc, g_bc);

    const size_t aggBytes = (size_t)N_NODES * H * sizeof(float);

    prep_kernel<<<4, 256>>>(We, be, Wi, bi, p_Wc, p_bc);
    node_proj_kernel<<<N_NODES / 8, 256>>>(node_feats, Wn, bn, p_node);

    cudaMemsetAsync(p_aggA, 0, aggBytes);
    h0_kernel<<<N_EDGES / 32, 256>>>(p_node, edge_feats, src, dst, Wi, p_Wc, p_bc,
                                     p_h0, p_aggA);

    // layer 0: gather aggA (sum of h0), h_in = h0, out -> hA, scatter -> aggB
    cudaMemsetAsync(p_aggB, 0, aggBytes);
    conv_kernel<<<N_EDGES / 32, 256>>>(Wl + 0 * H * H, bl + 0 * H, src, dst,
                                       p_aggA, p_h0, p_h0, p_hA, p_aggB);
    // layer 1
    cudaMemsetAsync(p_aggA, 0, aggBytes);
    conv_kernel<<<N_EDGES / 32, 256>>>(Wl + 1 * H * H, bl + 1 * H, src, dst,
                                       p_aggB, p_hA, p_h0, p_hB, p_aggA);
    // layer 2
    cudaMemsetAsync(p_aggB, 0, aggBytes);
    conv_kernel<<<N_EDGES / 32, 256>>>(Wl + 2 * H * H, bl + 2 * H, src, dst,
                                       p_aggA, p_hB, p_h0, p_hA, p_aggB);
    // layer 3
    cudaMemsetAsync(p_aggA, 0, aggBytes);
    conv_kernel<<<N_EDGES / 32, 256>>>(Wl + 3 * H * H, bl + 3 * H, src, dst,
                                       p_aggB, p_hA, p_h0, p_hB, p_aggA);

    cudaMemsetAsync(p_gpool, 0, (size_t)N_GRAPHS * H * sizeof(float));
    readout_kernel<<<N_NODES / 32, 256>>>(p_node, p_aggA, Wa, ba, gid, p_gpool);
    head_kernel<<<N_GRAPHS / 8, 256>>>(p_gpool, W1, b1, W2, b2, out);
}

// round 2
// speedup vs baseline: 1.5037x; 1.5037x over previous
#include <cuda_runtime.h>

#define N_NODES 400000
#define N_EDGES 1600000
#define N_GRAPHS 10000
#define H 64
#define NODE_DIM 74
#define EDGE_DIM 13
#define WPB 8        // warps per block
#define RPW 16       // rows (edges/nodes) per warp
#define ROWSTRIDE 20 // floats per k-row in sM staging (5 x 16B chunks, conflict-free)

typedef unsigned long long ull;

// ---------------- device scratch ----------------
__device__ float g_node[(size_t)N_NODES * H];
__device__ float g_h0[(size_t)N_EDGES * H];
__device__ float g_hA[(size_t)N_EDGES * H];
__device__ float g_hB[(size_t)N_EDGES * H];
__device__ float g_aggA[(size_t)N_NODES * H];
__device__ float g_aggB[(size_t)N_NODES * H];
__device__ float g_gpool[(size_t)N_GRAPHS * H];
__device__ float g_Wc[EDGE_DIM * H];
__device__ float g_bc[H];

__device__ __forceinline__ float lrelu(float v) { return fmaxf(v, 0.01f * v); }

__device__ __forceinline__ ull pack2(float x, float y) {
    ull r; asm("mov.b64 %0, {%1, %2};" : "=l"(r) : "f"(x), "f"(y)); return r;
}
__device__ __forceinline__ float2 unpack2(ull v) {
    float2 r; asm("mov.b64 {%0, %1}, %2;" : "=f"(r.x), "=f"(r.y) : "l"(v)); return r;
}
#define FFMA2(acc, a, b) asm("fma.rn.f32x2 %0, %1, %2, %0;" : "+l"(acc) : "l"(a), "l"(b))

// 16 FFMA2 on one k-row of 4 ulonglong2 chunks against duplicated (wx,wy)
#define KSTEP(q0, q1, q2, q3, wx, wy, A, B)                                   \
    FFMA2(A[0], q0.x, wx); FFMA2(A[1], q0.y, wx);                             \
    FFMA2(A[2], q1.x, wx); FFMA2(A[3], q1.y, wx);                             \
    FFMA2(A[4], q2.x, wx); FFMA2(A[5], q2.y, wx);                             \
    FFMA2(A[6], q3.x, wx); FFMA2(A[7], q3.y, wx);                             \
    FFMA2(B[0], q0.x, wy); FFMA2(B[1], q0.y, wy);                             \
    FFMA2(B[2], q1.x, wy); FFMA2(B[3], q1.y, wy);                             \
    FFMA2(B[4], q2.x, wy); FFMA2(B[5], q2.y, wy);                             \
    FFMA2(B[6], q3.x, wy); FFMA2(B[7], q3.y, wy)

// ---------------- prep: fold edge projection through Wi ----------------
__global__ void prep_kernel(const float* __restrict__ We, const float* __restrict__ be,
                            const float* __restrict__ Wi, const float* __restrict__ bi,
                            float* __restrict__ Wc, float* __restrict__ bc) {
    int tid = blockIdx.x * blockDim.x + threadIdx.x;
    if (tid < EDGE_DIM * H) {
        int d = tid >> 6, j = tid & 63;
        float s = 0.f;
        #pragma unroll 8
        for (int k = 0; k < H; k++) s += We[d * H + k] * Wi[(H + k) * H + j];
        Wc[tid] = s;
    }
    if (tid < H) {
        float s = bi[tid];
        #pragma unroll 8
        for (int k = 0; k < H; k++) s += be[k] * Wi[(H + k) * H + tid];
        bc[tid] = s;
    }
}

// ---------------- node projection (K=74) ----------------
__global__ __launch_bounds__(256) void node_proj_kernel(
    const float* __restrict__ nf, const float* __restrict__ Wn,
    const float* __restrict__ bn, float* __restrict__ node) {
    extern __shared__ __align__(16) float dsm[];
    float* sM = dsm;                               // 8*74*20 floats
    float2* sW = (float2*)(dsm + WPB * NODE_DIM * ROWSTRIDE);
    float* sb = (float*)(sW + NODE_DIM * 32);
    for (int idx = threadIdx.x; idx < NODE_DIM * 32; idx += 256) {
        int k = idx >> 5, j = idx & 31;
        sW[idx] = make_float2(Wn[k * H + j], Wn[k * H + j + 32]);
    }
    if (threadIdx.x < H) sb[threadIdx.x] = bn[threadIdx.x];
    __syncthreads();
    int warp = threadIdx.x >> 5, lane = threadIdx.x & 31;
    int nb = (blockIdx.x * WPB + warp) * RPW;
    float* myM = sM + warp * NODE_DIM * ROWSTRIDE;

    float4 b0, b1, b2;
    #pragma unroll
    for (int c = 0; c < 4; c++) {
        #pragma unroll
        for (int t = 0; t < 4; t++) {
            int n = nb + c * 4 + t;
            const float* row = nf + (size_t)n * NODE_DIM;
            ((float*)&b0)[t] = row[lane];
            ((float*)&b1)[t] = row[lane + 32];
            ((float*)&b2)[t] = (lane < NODE_DIM - 64) ? row[lane + 64] : 0.f;
        }
        *(float4*)(myM + (lane * 5 + c) * 4) = b0;
        *(float4*)(myM + ((lane + 32) * 5 + c) * 4) = b1;
        if (lane < NODE_DIM - 64) *(float4*)(myM + ((lane + 64) * 5 + c) * 4) = b2;
    }
    __syncwarp();

    float bj0 = sb[lane], bj1 = sb[lane + 32];
    ull A[8], B[8];
    #pragma unroll
    for (int p = 0; p < 8; p++) { A[p] = pack2(bj0, bj0); B[p] = pack2(bj1, bj1); }
    #pragma unroll 2
    for (int k = 0; k < NODE_DIM; k++) {
        const ulonglong2* row = (const ulonglong2*)(myM + k * ROWSTRIDE);
        ulonglong2 q0 = row[0], q1 = row[1], q2 = row[2], q3 = row[3];
        float2 w = sW[k * 32 + lane];
        ull wx = pack2(w.x, w.x), wy = pack2(w.y, w.y);
        KSTEP(q0, q1, q2, q3, wx, wy, A, B);
    }
    #pragma unroll
    for (int p = 0; p < 8; p++) {
        float2 vA = unpack2(A[p]), vB = unpack2(B[p]);
        int n0 = nb + 2 * p, n1 = n0 + 1;
        node[n0 * H + lane] = vA.x;  node[n0 * H + lane + 32] = vB.x;
        node[n1 * H + lane] = vA.y;  node[n1 * H + lane + 32] = vB.y;
    }
}

// ---------------- h0 (K=77): lrelu(node[src]@Wi_top + ef@Wc + bc), scatter ----------------
#define K_H0 (H + EDGE_DIM)
__global__ __launch_bounds__(256) void h0_kernel(
    const float* __restrict__ node, const float* __restrict__ ef,
    const int* __restrict__ src, const int* __restrict__ dst,
    const float* __restrict__ Wi, const float* __restrict__ Wc,
    const float* __restrict__ bc, float* __restrict__ h0,
    float* __restrict__ agg_out) {
    extern __shared__ __align__(16) float dsm[];
    float* sM = dsm;
    float2* sW = (float2*)(dsm + WPB * K_H0 * ROWSTRIDE);
    float* sb = (float*)(sW + K_H0 * 32);
    for (int idx = threadIdx.x; idx < K_H0 * 32; idx += 256) {
        int k = idx >> 5, j = idx & 31;
        float wx, wy;
        if (k < H) { wx = Wi[k * H + j]; wy = Wi[k * H + j + 32]; }
        else       { wx = Wc[(k - H) * H + j]; wy = Wc[(k - H) * H + j + 32]; }
        sW[idx] = make_float2(wx, wy);
    }
    if (threadIdx.x < H) sb[threadIdx.x] = bc[threadIdx.x];
    __syncthreads();
    int warp = threadIdx.x >> 5, lane = threadIdx.x & 31;
    int eb = (blockIdx.x * WPB + warp) * RPW;
    float* myM = sM + warp * K_H0 * ROWSTRIDE;
    int sidx = src[eb + (lane & 15)];
    int didx = dst[eb + (lane & 15)];

    float4 b0, b1, b2;
    #pragma unroll
    for (int c = 0; c < 4; c++) {
        #pragma unroll
        for (int t = 0; t < 4; t++) {
            int i = c * 4 + t;
            int s = __shfl_sync(0xffffffffu, sidx, i);
            int e = eb + i;
            ((float*)&b0)[t] = node[s * H + lane];
            ((float*)&b1)[t] = node[s * H + lane + 32];
            ((float*)&b2)[t] = (lane < EDGE_DIM) ? ef[e * EDGE_DIM + lane] : 0.f;
        }
        *(float4*)(myM + (lane * 5 + c) * 4) = b0;
        *(float4*)(myM + ((lane + 32) * 5 + c) * 4) = b1;
        if (lane < EDGE_DIM) *(float4*)(myM + ((lane + 64) * 5 + c) * 4) = b2;
    }
    __syncwarp();

    float bj0 = sb[lane], bj1 = sb[lane + 32];
    ull A[8], B[8];
    #pragma unroll
    for (int p = 0; p < 8; p++) { A[p] = pack2(bj0, bj0); B[p] = pack2(bj1, bj1); }
    #pragma unroll 7
    for (int k = 0; k < K_H0; k++) {
        const ulonglong2* row = (const ulonglong2*)(myM + k * ROWSTRIDE);
        ulonglong2 q0 = row[0], q1 = row[1], q2 = row[2], q3 = row[3];
        float2 w = sW[k * 32 + lane];
        ull wx = pack2(w.x, w.x), wy = pack2(w.y, w.y);
        KSTEP(q0, q1, q2, q3, wx, wy, A, B);
    }
    #pragma unroll
    for (int p = 0; p < 8; p++) {
        float2 vA = unpack2(A[p]), vB = unpack2(B[p]);
        int e0 = eb + 2 * p, e1 = e0 + 1;
        int d0 = __shfl_sync(0xffffffffu, didx, 2 * p);
        int d1 = __shfl_sync(0xffffffffu, didx, 2 * p + 1);
        float o00 = lrelu(vA.x), o01 = lrelu(vB.x);
        float o10 = lrelu(vA.y), o11 = lrelu(vB.y);
        h0[e0 * H + lane] = o00; h0[e0 * H + lane + 32] = o01;
        h0[e1 * H + lane] = o10; h0[e1 * H + lane + 32] = o11;
        atomicAdd(&agg_out[d0 * H + lane], o00);
        atomicAdd(&agg_out[d0 * H + lane + 32], o01);
        atomicAdd(&agg_out[d1 * H + lane], o10);
        atomicAdd(&agg_out[d1 * H + lane + 32], o11);
    }
}

// ---------------- conv layer (K=64) ----------------
__global__ __launch_bounds__(256) void conv_kernel(
    const float* __restrict__ W, const float* __restrict__ b,
    const int* __restrict__ src, const int* __restrict__ dst,
    const float* __restrict__ agg_in, const float* __restrict__ h_in,
    const float* __restrict__ h0, float* __restrict__ h_out,
    float* __restrict__ agg_out) {
    extern __shared__ __align__(16) float dsm[];
    float* sM = dsm;
    float2* sW = (float2*)(dsm + WPB * H * ROWSTRIDE);
    float* sb = (float*)(sW + H * 32);
    for (int idx = threadIdx.x; idx < H * 32; idx += 256) {
        int k = idx >> 5, j = idx & 31;
        sW[idx] = make_float2(W[k * H + j], W[k * H + j + 32]);
    }
    if (threadIdx.x < H) sb[threadIdx.x] = b[threadIdx.x];
    __syncthreads();
    int warp = threadIdx.x >> 5, lane = threadIdx.x & 31;
    int eb = (blockIdx.x * WPB + warp) * RPW;
    float* myM = sM + warp * H * ROWSTRIDE;
    int sidx = src[eb + (lane & 15)];
    int didx = dst[eb + (lane & 15)];

    float4 b0, b1;
    #pragma unroll
    for (int c = 0; c < 4; c++) {
        #pragma unroll
        for (int t = 0; t < 4; t++) {
            int i = c * 4 + t;
            int s = __shfl_sync(0xffffffffu, sidx, i);
            int e = eb + i, r = e ^ 1;
            ((float*)&b0)[t] = agg_in[s * H + lane]      - h_in[r * H + lane];
            ((float*)&b1)[t] = agg_in[s * H + lane + 32] - h_in[r * H + lane + 32];
        }
        *(float4*)(myM + (lane * 5 + c) * 4) = b0;
        *(float4*)(myM + ((lane + 32) * 5 + c) * 4) = b1;
    }
    __syncwarp();

    float bj0 = sb[lane], bj1 = sb[lane + 32];
    ull A[8], B[8];
    #pragma unroll
    for (int p = 0; p < 8; p++) { A[p] = pack2(bj0, bj0); B[p] = pack2(bj1, bj1); }
    #pragma unroll 8
    for (int k = 0; k < H; k++) {
        const ulonglong2* row = (const ulonglong2*)(myM + k * ROWSTRIDE);
        ulonglong2 q0 = row[0], q1 = row[1], q2 = row[2], q3 = row[3];
        float2 w = sW[k * 32 + lane];
        ull wx = pack2(w.x, w.x), wy = pack2(w.y, w.y);
        KSTEP(q0, q1, q2, q3, wx, wy, A, B);
    }
    #pragma unroll
    for (int p = 0; p < 8; p++) {
        float2 vA = unpack2(A[p]), vB = unpack2(B[p]);
        int e0 = eb + 2 * p, e1 = e0 + 1;
        int d0 = __shfl_sync(0xffffffffu, didx, 2 * p);
        int d1 = __shfl_sync(0xffffffffu, didx, 2 * p + 1);
        float o00 = lrelu(h0[e0 * H + lane]      + vA.x);
        float o01 = lrelu(h0[e0 * H + lane + 32] + vB.x);
        float o10 = lrelu(h0[e1 * H + lane]      + vA.y);
        float o11 = lrelu(h0[e1 * H + lane + 32] + vB.y);
        h_out[e0 * H + lane] = o00; h_out[e0 * H + lane + 32] = o01;
        h_out[e1 * H + lane] = o10; h_out[e1 * H + lane + 32] = o11;
        atomicAdd(&agg_out[d0 * H + lane], o00);
        atomicAdd(&agg_out[d0 * H + lane + 32], o01);
        atomicAdd(&agg_out[d1 * H + lane], o10);
        atomicAdd(&agg_out[d1 * H + lane + 32], o11);
    }
}

// ---------------- node readout + graph pooling (K=128, two stages) ----------------
__global__ __launch_bounds__(256) void readout_kernel(
    const float* __restrict__ node, const float* __restrict__ agg,
    const float* __restrict__ Wa, const float* __restrict__ ba,
    const int* __restrict__ gid, float* __restrict__ gpool) {
    extern __shared__ __align__(16) float dsm[];
    float* sM = dsm;
    float2* sW = (float2*)(dsm + WPB * H * ROWSTRIDE);
    float* sb = (float*)(sW + 2 * H * 32);
    for (int idx = threadIdx.x; idx < 2 * H * 32; idx += 256) {
        int k = idx >> 5, j = idx & 31;
        sW[idx] = make_float2(Wa[k * H + j], Wa[k * H + j + 32]);
    }
    if (threadIdx.x < H) sb[threadIdx.x] = ba[threadIdx.x];
    __syncthreads();
    int warp = threadIdx.x >> 5, lane = threadIdx.x & 31;
    int nb = (blockIdx.x * WPB + warp) * RPW;
    float* myM = sM + warp * H * ROWSTRIDE;
    int gidx = gid[nb + (lane & 15)];

    float bj0 = sb[lane], bj1 = sb[lane + 32];
    ull A[8], B[8];
    #pragma unroll
    for (int p = 0; p < 8; p++) { A[p] = pack2(bj0, bj0); B[p] = pack2(bj1, bj1); }

    #pragma unroll
    for (int stage = 0; stage < 2; stage++) {
        const float* in = stage ? agg : node;
        float4 b0, b1;
        #pragma unroll
        for (int c = 0; c < 4; c++) {
            #pragma unroll
            for (int t = 0; t < 4; t++) {
                int n = nb + c * 4 + t;
                ((float*)&b0)[t] = in[n * H + lane];
                ((float*)&b1)[t] = in[n * H + lane + 32];
            }
            *(float4*)(myM + (lane * 5 + c) * 4) = b0;
            *(float4*)(myM + ((lane + 32) * 5 + c) * 4) = b1;
        }
        __syncwarp();
        #pragma unroll 8
        for (int k = 0; k < H; k++) {
            const ulonglong2* row = (const ulonglong2*)(myM + k * ROWSTRIDE);
            ulonglong2 q0 = row[0], q1 = row[1], q2 = row[2], q3 = row[3];
            float2 w = sW[(stage * H + k) * 32 + lane];
            ull wx = pack2(w.x, w.x), wy = pack2(w.y, w.y);
            KSTEP(q0, q1, q2, q3, wx, wy, A, B);
        }
        __syncwarp();   // stage-0 reads done before stage-1 overwrites
    }
    #pragma unroll
    for (int p = 0; p < 8; p++) {
        float2 vA = unpack2(A[p]), vB = unpack2(B[p]);
        int g0 = __shfl_sync(0xffffffffu, gidx, 2 * p);
        int g1 = __shfl_sync(0xffffffffu, gidx, 2 * p + 1);
        atomicAdd(&gpool[g0 * H + lane], lrelu(vA.x));
        atomicAdd(&gpool[g0 * H + lane + 32], lrelu(vB.x));
        atomicAdd(&gpool[g1 * H + lane], lrelu(vA.y));
        atomicAdd(&gpool[g1 * H + lane + 32], lrelu(vB.y));
    }
}

// ---------------- head ----------------
__global__ __launch_bounds__(256) void head_kernel(
    const float* __restrict__ g, const float* __restrict__ W1,
    const float* __restrict__ b1, const float* __restrict__ W2,
    const float* __restrict__ b2, float* __restrict__ out) {
    __shared__ float2 sW[H * 32];
    __shared__ float sb[H];
    __shared__ float sW2[H];
    for (int idx = threadIdx.x; idx < H * 32; idx += 256) {
        int k = idx >> 5, j = idx & 31;
        sW[idx] = make_float2(W1[k * H + j], W1[k * H + j + 32]);
    }
    if (threadIdx.x < H) { sb[threadIdx.x] = b1[threadIdx.x]; sW2[threadIdx.x] = W2[threadIdx.x]; }
    __syncthreads();
    int warp = threadIdx.x >> 5, lane = threadIdx.x & 31;
    int gi = blockIdx.x * 8 + warp;
    const float* row = g + gi * H;
    float f0 = row[lane], f1 = row[lane + 32];
    float a0 = sb[lane], a1 = sb[lane + 32];
    #pragma unroll
    for (int k = 0; k < H; k++) {
        float fk = __shfl_sync(0xffffffffu, (k < 32 ? f0 : f1), k & 31);
        float2 w = sW[k * 32 + lane];
        a0 += fk * w.x; a1 += fk * w.y;
    }
    a0 = lrelu(a0); a1 = lrelu(a1);
    float p = a0 * sW2[lane] + a1 * sW2[lane + 32];
    #pragma unroll
    for (int o = 16; o; o >>= 1) p += __shfl_xor_sync(0xffffffffu, p, o);
    if (lane == 0) out[gi] = p + b2[0];
}

// ---------------- launch ----------------
extern "C" void kernel_launch(void* const* d_in, const int* in_sizes, int n_in,
                              void* d_out, int out_size) {
    const float* node_feats = (const float*)d_in[0];
    const float* edge_feats = (const float*)d_in[1];
    const int*   src        = (const int*)d_in[2];
    const int*   dst        = (const int*)d_in[3];
    const int*   gid        = (const int*)d_in[4];
    const float* Wn = (const float*)d_in[5];
    const float* bn = (const float*)d_in[6];
    const float* We = (const float*)d_in[7];
    const float* be = (const float*)d_in[8];
    const float* Wi = (const float*)d_in[9];
    const float* bi = (const float*)d_in[10];
    const float* Wa = (const float*)d_in[11];
    const float* ba = (const float*)d_in[12];
    const float* Wl = (const float*)d_in[13];
    const float* bl = (const float*)d_in[14];
    const float* W1 = (const float*)d_in[15];
    const float* b1 = (const float*)d_in[16];
    const float* W2 = (const float*)d_in[17];
    const float* b2 = (const float*)d_in[18];
    float* out = (float*)d_out;

    float *p_node, *p_h0, *p_hA, *p_hB, *p_aggA, *p_aggB, *p_gpool, *p_Wc, *p_bc;
    cudaGetSymbolAddress((void**)&p_node, g_node);
    cudaGetSymbolAddress((void**)&p_h0, g_h0);
    cudaGetSymbolAddress((void**)&p_hA, g_hA);
    cudaGetSymbolAddress((void**)&p_hB, g_hB);
    cudaGetSymbolAddress((void**)&p_aggA, g_aggA);
    cudaGetSymbolAddress((void**)&p_aggB, g_aggB);
    cudaGetSymbolAddress((void**)&p_gpool, g_gpool);
    cudaGetSymbolAddress((void**)&p_Wc, g_Wc);
    cudaGetSymbolAddress((void**)&p_bc, g_bc);

    const int SM_NP   = (WPB * NODE_DIM * ROWSTRIDE + NODE_DIM * 64 + H) * 4;
    const int SM_H0   = (WPB * K_H0 * ROWSTRIDE + K_H0 * 64 + H) * 4;
    const int SM_CONV = (WPB * H * ROWSTRIDE + H * 64 + H) * 4;
    const int SM_RO   = (WPB * H * ROWSTRIDE + 2 * H * 64 + H) * 4;
    cudaFuncSetAttribute(node_proj_kernel, cudaFuncAttributeMaxDynamicSharedMemorySize, SM_NP);
    cudaFuncSetAttribute(h0_kernel,       cudaFuncAttributeMaxDynamicSharedMemorySize, SM_H0);
    cudaFuncSetAttribute(conv_kernel,     cudaFuncAttributeMaxDynamicSharedMemorySize, SM_CONV);
    cudaFuncSetAttribute(readout_kernel,  cudaFuncAttributeMaxDynamicSharedMemorySize, SM_RO);

    const size_t aggBytes = (size_t)N_NODES * H * sizeof(float);
    const int EGRID = N_EDGES / (WPB * RPW);   // 12500
    const int NGRID = N_NODES / (WPB * RPW);   // 3125

    prep_kernel<<<4, 256>>>(We, be, Wi, bi, p_Wc, p_bc);
    node_proj_kernel<<<NGRID, 256, SM_NP>>>(node_feats, Wn, bn, p_node);

    cudaMemsetAsync(p_aggA, 0, aggBytes);
    h0_kernel<<<EGRID, 256, SM_H0>>>(p_node, edge_feats, src, dst, Wi, p_Wc, p_bc,
                                     p_h0, p_aggA);

    cudaMemsetAsync(p_aggB, 0, aggBytes);
    conv_kernel<<<EGRID, 256, SM_CONV>>>(Wl + 0 * H * H, bl + 0 * H, src, dst,
                                         p_aggA, p_h0, p_h0, p_hA, p_aggB);
    cudaMemsetAsync(p_aggA, 0, aggBytes);
    conv_kernel<<<EGRID, 256, SM_CONV>>>(Wl + 1 * H * H, bl + 1 * H, src, dst,
                                         p_aggB, p_hA, p_h0, p_hB, p_aggA);
    cudaMemsetAsync(p_aggB, 0, aggBytes);
    conv_kernel<<<EGRID, 256, SM_CONV>>>(Wl + 2 * H * H, bl + 2 * H, src, dst,
                                         p_aggA, p_hB, p_h0, p_hA, p_aggB);
    cudaMemsetAsync(p_aggA, 0, aggBytes);
    conv_kernel<<<EGRID, 256, SM_CONV>>>(Wl + 3 * H * H, bl + 3 * H, src, dst,
                                         p_aggB, p_hA, p_h0, p_hB, p_aggA);

    cudaMemsetAsync(p_gpool, 0, (size_t)N_GRAPHS * H * sizeof(float));
    readout_kernel<<<NGRID, 256, SM_RO>>>(p_node, p_aggA, Wa, ba, gid, p_gpool);
    head_kernel<<<N_GRAPHS / 8, 256>>>(p_gpool, W1, b1, W2, b2, out);
}

// round 3
// speedup vs baseline: 1.6166x; 1.0751x over previous
#include <cuda_runtime.h>
#include <cuda_fp16.h>

#define N_NODES 400000
#define N_EDGES 1600000
#define N_GRAPHS 10000
#define H 64
#define NODE_DIM 74
#define EDGE_DIM 13
#define WPB 8        // warps per block
#define RPW 16       // rows (edges/nodes) per warp
#define ROWSTRIDE 20 // floats per k-row in sM staging (5 x 16B chunks, conflict-free)

typedef unsigned long long ull;

// ---------------- device scratch ----------------
__device__ __half g_node[(size_t)N_NODES * H];   // fp16 projected node features
__device__ __half g_h0[(size_t)N_EDGES * H];     // fp16 edge hidden states
__device__ __half g_hA[(size_t)N_EDGES * H];
__device__ __half g_hB[(size_t)N_EDGES * H];
__device__ float g_aggA[(size_t)N_NODES * H];    // fp32 segment sums (atomics)
__device__ float g_aggB[(size_t)N_NODES * H];
__device__ float g_gpool[(size_t)N_GRAPHS * H];
__device__ float g_Wc[EDGE_DIM * H];
__device__ float g_bc[H];

__device__ __forceinline__ float lrelu(float v) { return fmaxf(v, 0.01f * v); }

__device__ __forceinline__ ull pack2(float x, float y) {
    ull r; asm("mov.b64 %0, {%1, %2};" : "=l"(r) : "f"(x), "f"(y)); return r;
}
__device__ __forceinline__ float2 unpack2(ull v) {
    float2 r; asm("mov.b64 {%0, %1}, %2;" : "=f"(r.x), "=f"(r.y) : "l"(v)); return r;
}
#define FFMA2(acc, a, b) asm("fma.rn.f32x2 %0, %1, %2, %0;" : "+l"(acc) : "l"(a), "l"(b))

#define KSTEP(q0, q1, q2, q3, wx, wy, A, B)                                   \
    FFMA2(A[0], q0.x, wx); FFMA2(A[1], q0.y, wx);                             \
    FFMA2(A[2], q1.x, wx); FFMA2(A[3], q1.y, wx);                             \
    FFMA2(A[4], q2.x, wx); FFMA2(A[5], q2.y, wx);                             \
    FFMA2(A[6], q3.x, wx); FFMA2(A[7], q3.y, wx);                             \
    FFMA2(B[0], q0.x, wy); FFMA2(B[1], q0.y, wy);                             \
    FFMA2(B[2], q1.x, wy); FFMA2(B[3], q1.y, wy);                             \
    FFMA2(B[4], q2.x, wy); FFMA2(B[5], q2.y, wy);                             \
    FFMA2(B[6], q3.x, wy); FFMA2(B[7], q3.y, wy)

// ---------------- prep: fold edge projection through Wi ----------------
__global__ void prep_kernel(const float* __restrict__ We, const float* __restrict__ be,
                            const float* __restrict__ Wi, const float* __restrict__ bi,
                            float* __restrict__ Wc, float* __restrict__ bc) {
    int tid = blockIdx.x * blockDim.x + threadIdx.x;
    if (tid < EDGE_DIM * H) {
        int d = tid >> 6, j = tid & 63;
        float s = 0.f;
        #pragma unroll 8
        for (int k = 0; k < H; k++) s += We[d * H + k] * Wi[(H + k) * H + j];
        Wc[tid] = s;
    }
    if (tid < H) {
        float s = bi[tid];
        #pragma unroll 8
        for (int k = 0; k < H; k++) s += be[k] * Wi[(H + k) * H + tid];
        bc[tid] = s;
    }
}

// ---------------- node projection (K=74), fp16 output ----------------
__global__ __launch_bounds__(256) void node_proj_kernel(
    const float* __restrict__ nf, const float* __restrict__ Wn,
    const float* __restrict__ bn, __half* __restrict__ node) {
    extern __shared__ __align__(16) float dsm[];
    float* sM = dsm;
    float2* sW = (float2*)(dsm + WPB * NODE_DIM * ROWSTRIDE);
    float* sb = (float*)(sW + NODE_DIM * 32);
    for (int idx = threadIdx.x; idx < NODE_DIM * 32; idx += 256) {
        int k = idx >> 5, j = idx & 31;
        sW[idx] = make_float2(Wn[k * H + j], Wn[k * H + j + 32]);
    }
    if (threadIdx.x < H) sb[threadIdx.x] = bn[threadIdx.x];
    __syncthreads();
    int warp = threadIdx.x >> 5, lane = threadIdx.x & 31;
    int nb = (blockIdx.x * WPB + warp) * RPW;
    float* myM = sM + warp * NODE_DIM * ROWSTRIDE;

    float4 b0, b1, b2;
    #pragma unroll
    for (int c = 0; c < 4; c++) {
        #pragma unroll
        for (int t = 0; t < 4; t++) {
            int n = nb + c * 4 + t;
            const float* row = nf + (size_t)n * NODE_DIM;
            ((float*)&b0)[t] = row[lane];
            ((float*)&b1)[t] = row[lane + 32];
            ((float*)&b2)[t] = (lane < NODE_DIM - 64) ? row[lane + 64] : 0.f;
        }
        *(float4*)(myM + (lane * 5 + c) * 4) = b0;
        *(float4*)(myM + ((lane + 32) * 5 + c) * 4) = b1;
        if (lane < NODE_DIM - 64) *(float4*)(myM + ((lane + 64) * 5 + c) * 4) = b2;
    }
    __syncwarp();

    float bj0 = sb[lane], bj1 = sb[lane + 32];
    ull A[8], B[8];
    #pragma unroll
    for (int p = 0; p < 8; p++) { A[p] = pack2(bj0, bj0); B[p] = pack2(bj1, bj1); }
    #pragma unroll 2
    for (int k = 0; k < NODE_DIM; k++) {
        const ulonglong2* row = (const ulonglong2*)(myM + k * ROWSTRIDE);
        ulonglong2 q0 = row[0], q1 = row[1], q2 = row[2], q3 = row[3];
        float2 w = sW[k * 32 + lane];
        ull wx = pack2(w.x, w.x), wy = pack2(w.y, w.y);
        KSTEP(q0, q1, q2, q3, wx, wy, A, B);
    }
    #pragma unroll
    for (int p = 0; p < 8; p++) {
        float2 vA = unpack2(A[p]), vB = unpack2(B[p]);
        int n0 = nb + 2 * p, n1 = n0 + 1;
        node[n0 * H + lane]      = __float2half_rn(vA.x);
        node[n0 * H + lane + 32] = __float2half_rn(vB.x);
        node[n1 * H + lane]      = __float2half_rn(vA.y);
        node[n1 * H + lane + 32] = __float2half_rn(vB.y);
    }
}

// ---------------- h0 (K=77): lrelu(node[src]@Wi_top + ef@Wc + bc), scatter ----------------
#define K_H0 (H + EDGE_DIM)
__global__ __launch_bounds__(256) void h0_kernel(
    const __half* __restrict__ node, const float* __restrict__ ef,
    const int* __restrict__ src, const int* __restrict__ dst,
    const float* __restrict__ Wi, const float* __restrict__ Wc,
    const float* __restrict__ bc, __half* __restrict__ h0,
    float* __restrict__ agg_out) {
    extern __shared__ __align__(16) float dsm[];
    float* sM = dsm;
    float2* sW = (float2*)(dsm + WPB * K_H0 * ROWSTRIDE);
    float* sb = (float*)(sW + K_H0 * 32);
    for (int idx = threadIdx.x; idx < K_H0 * 32; idx += 256) {
        int k = idx >> 5, j = idx & 31;
        float wx, wy;
        if (k < H) { wx = Wi[k * H + j]; wy = Wi[k * H + j + 32]; }
        else       { wx = Wc[(k - H) * H + j]; wy = Wc[(k - H) * H + j + 32]; }
        sW[idx] = make_float2(wx, wy);
    }
    if (threadIdx.x < H) sb[threadIdx.x] = bc[threadIdx.x];
    __syncthreads();
    int warp = threadIdx.x >> 5, lane = threadIdx.x & 31;
    int eb = (blockIdx.x * WPB + warp) * RPW;
    float* myM = sM + warp * K_H0 * ROWSTRIDE;
    int sidx = src[eb + (lane & 15)];
    int didx = dst[eb + (lane & 15)];

    float4 b0, b1, b2;
    #pragma unroll
    for (int c = 0; c < 4; c++) {
        #pragma unroll
        for (int t = 0; t < 4; t++) {
            int i = c * 4 + t;
            int s = __shfl_sync(0xffffffffu, sidx, i);
            int e = eb + i;
            ((float*)&b0)[t] = __half2float(node[s * H + lane]);
            ((float*)&b1)[t] = __half2float(node[s * H + lane + 32]);
            ((float*)&b2)[t] = (lane < EDGE_DIM) ? ef[e * EDGE_DIM + lane] : 0.f;
        }
        *(float4*)(myM + (lane * 5 + c) * 4) = b0;
        *(float4*)(myM + ((lane + 32) * 5 + c) * 4) = b1;
        if (lane < EDGE_DIM) *(float4*)(myM + ((lane + 64) * 5 + c) * 4) = b2;
    }
    __syncwarp();

    float bj0 = sb[lane], bj1 = sb[lane + 32];
    ull A[8], B[8];
    #pragma unroll
    for (int p = 0; p < 8; p++) { A[p] = pack2(bj0, bj0); B[p] = pack2(bj1, bj1); }
    #pragma unroll 7
    for (int k = 0; k < K_H0; k++) {
        const ulonglong2* row = (const ulonglong2*)(myM + k * ROWSTRIDE);
        ulonglong2 q0 = row[0], q1 = row[1], q2 = row[2], q3 = row[3];
        float2 w = sW[k * 32 + lane];
        ull wx = pack2(w.x, w.x), wy = pack2(w.y, w.y);
        KSTEP(q0, q1, q2, q3, wx, wy, A, B);
    }
    #pragma unroll
    for (int p = 0; p < 8; p++) {
        float2 vA = unpack2(A[p]), vB = unpack2(B[p]);
        int e0 = eb + 2 * p, e1 = e0 + 1;
        int d0 = __shfl_sync(0xffffffffu, didx, 2 * p);
        int d1 = __shfl_sync(0xffffffffu, didx, 2 * p + 1);
        float o00 = lrelu(vA.x), o01 = lrelu(vB.x);
        float o10 = lrelu(vA.y), o11 = lrelu(vB.y);
        h0[e0 * H + lane]      = __float2half_rn(o00);
        h0[e0 * H + lane + 32] = __float2half_rn(o01);
        h0[e1 * H + lane]      = __float2half_rn(o10);
        h0[e1 * H + lane + 32] = __float2half_rn(o11);
        atomicAdd(&agg_out[d0 * H + lane], o00);
        atomicAdd(&agg_out[d0 * H + lane + 32], o01);
        atomicAdd(&agg_out[d1 * H + lane], o10);
        atomicAdd(&agg_out[d1 * H + lane + 32], o11);
    }
}

// ---------------- conv layer (K=64) ----------------
__global__ __launch_bounds__(256) void conv_kernel(
    const float* __restrict__ W, const float* __restrict__ b,
    const int* __restrict__ src, const int* __restrict__ dst,
    const float* __restrict__ agg_in, const __half* __restrict__ h_in,
    const __half* __restrict__ h0, __half* __restrict__ h_out,
    float* __restrict__ agg_out) {
    extern __shared__ __align__(16) float dsm[];
    float* sM = dsm;
    float2* sW = (float2*)(dsm + WPB * H * ROWSTRIDE);
    float* sb = (float*)(sW + H * 32);
    for (int idx = threadIdx.x; idx < H * 32; idx += 256) {
        int k = idx >> 5, j = idx & 31;
        sW[idx] = make_float2(W[k * H + j], W[k * H + j + 32]);
    }
    if (threadIdx.x < H) sb[threadIdx.x] = b[threadIdx.x];
    __syncthreads();
    int warp = threadIdx.x >> 5, lane = threadIdx.x & 31;
    int eb = (blockIdx.x * WPB + warp) * RPW;
    float* myM = sM + warp * H * ROWSTRIDE;
    int sidx = src[eb + (lane & 15)];
    int didx = dst[eb + (lane & 15)];

    float4 b0, b1;
    #pragma unroll
    for (int c = 0; c < 4; c++) {
        #pragma unroll
        for (int t = 0; t < 4; t++) {
            int i = c * 4 + t;
            int s = __shfl_sync(0xffffffffu, sidx, i);
            int e = eb + i, r = e ^ 1;
            ((float*)&b0)[t] = agg_in[s * H + lane]      - __half2float(h_in[r * H + lane]);
            ((float*)&b1)[t] = agg_in[s * H + lane + 32] - __half2float(h_in[r * H + lane + 32]);
        }
        *(float4*)(myM + (lane * 5 + c) * 4) = b0;
        *(float4*)(myM + ((lane + 32) * 5 + c) * 4) = b1;
    }
    __syncwarp();

    float bj0 = sb[lane], bj1 = sb[lane + 32];
    ull A[8], B[8];
    #pragma unroll
    for (int p = 0; p < 8; p++) { A[p] = pack2(bj0, bj0); B[p] = pack2(bj1, bj1); }
    #pragma unroll 8
    for (int k = 0; k < H; k++) {
        const ulonglong2* row = (const ulonglong2*)(myM + k * ROWSTRIDE);
        ulonglong2 q0 = row[0], q1 = row[1], q2 = row[2], q3 = row[3];
        float2 w = sW[k * 32 + lane];
        ull wx = pack2(w.x, w.x), wy = pack2(w.y, w.y);
        KSTEP(q0, q1, q2, q3, wx, wy, A, B);
    }
    #pragma unroll
    for (int p = 0; p < 8; p++) {
        float2 vA = unpack2(A[p]), vB = unpack2(B[p]);
        int e0 = eb + 2 * p, e1 = e0 + 1;
        int d0 = __shfl_sync(0xffffffffu, didx, 2 * p);
        int d1 = __shfl_sync(0xffffffffu, didx, 2 * p + 1);
        float o00 = lrelu(__half2float(h0[e0 * H + lane])      + vA.x);
        float o01 = lrelu(__half2float(h0[e0 * H + lane + 32]) + vB.x);
        float o10 = lrelu(__half2float(h0[e1 * H + lane])      + vA.y);
        float o11 = lrelu(__half2float(h0[e1 * H + lane + 32]) + vB.y);
        h_out[e0 * H + lane]      = __float2half_rn(o00);
        h_out[e0 * H + lane + 32] = __float2half_rn(o01);
        h_out[e1 * H + lane]      = __float2half_rn(o10);
        h_out[e1 * H + lane + 32] = __float2half_rn(o11);
        atomicAdd(&agg_out[d0 * H + lane], o00);
        atomicAdd(&agg_out[d0 * H + lane + 32], o01);
        atomicAdd(&agg_out[d1 * H + lane], o10);
        atomicAdd(&agg_out[d1 * H + lane + 32], o11);
    }
}

// ---------------- node readout + graph pooling (K=128, two stages) ----------------
__global__ __launch_bounds__(256) void readout_kernel(
    const __half* __restrict__ node, const float* __restrict__ agg,
    const float* __restrict__ Wa, const float* __restrict__ ba,
    const int* __restrict__ gid, float* __restrict__ gpool) {
    extern __shared__ __align__(16) float dsm[];
    float* sM = dsm;
    float2* sW = (float2*)(dsm + WPB * H * ROWSTRIDE);
    float* sb = (float*)(sW + 2 * H * 32);
    for (int idx = threadIdx.x; idx < 2 * H * 32; idx += 256) {
        int k = idx >> 5, j = idx & 31;
        sW[idx] = make_float2(Wa[k * H + j], Wa[k * H + j + 32]);
    }
    if (threadIdx.x < H) sb[threadIdx.x] = ba[threadIdx.x];
    __syncthreads();
    int warp = threadIdx.x >> 5, lane = threadIdx.x & 31;
    int nb = (blockIdx.x * WPB + warp) * RPW;
    float* myM = sM + warp * H * ROWSTRIDE;
    int gidx = gid[nb + (lane & 15)];

    float bj0 = sb[lane], bj1 = sb[lane + 32];
    ull A[8], B[8];
    #pragma unroll
    for (int p = 0; p < 8; p++) { A[p] = pack2(bj0, bj0); B[p] = pack2(bj1, bj1); }

    #pragma unroll
    for (int stage = 0; stage < 2; stage++) {
        float4 b0, b1;
        #pragma unroll
        for (int c = 0; c < 4; c++) {
            #pragma unroll
            for (int t = 0; t < 4; t++) {
                int n = nb + c * 4 + t;
                if (stage == 0) {
                    ((float*)&b0)[t] = __half2float(node[n * H + lane]);
                    ((float*)&b1)[t] = __half2float(node[n * H + lane + 32]);
                } else {
                    ((float*)&b0)[t] = agg[n * H + lane];
                    ((float*)&b1)[t] = agg[n * H + lane + 32];
                }
            }
            *(float4*)(myM + (lane * 5 + c) * 4) = b0;
            *(float4*)(myM + ((lane + 32) * 5 + c) * 4) = b1;
        }
        __syncwarp();
        #pragma unroll 8
        for (int k = 0; k < H; k++) {
            const ulonglong2* row = (const ulonglong2*)(myM + k * ROWSTRIDE);
            ulonglong2 q0 = row[0], q1 = row[1], q2 = row[2], q3 = row[3];
            float2 w = sW[(stage * H + k) * 32 + lane];
            ull wx = pack2(w.x, w.x), wy = pack2(w.y, w.y);
            KSTEP(q0, q1, q2, q3, wx, wy, A, B);
        }
        __syncwarp();
    }
    #pragma unroll
    for (int p = 0; p < 8; p++) {
        float2 vA = unpack2(A[p]), vB = unpack2(B[p]);
        int g0 = __shfl_sync(0xffffffffu, gidx, 2 * p);
        int g1 = __shfl_sync(0xffffffffu, gidx, 2 * p + 1);
        atomicAdd(&gpool[g0 * H + lane], lrelu(vA.x));
        atomicAdd(&gpool[g0 * H + lane + 32], lrelu(vB.x));
        atomicAdd(&gpool[g1 * H + lane], lrelu(vA.y));
        atomicAdd(&gpool[g1 * H + lane + 32], lrelu(vB.y));
    }
}

// ---------------- head ----------------
__global__ __launch_bounds__(256) void head_kernel(
    const float* __restrict__ g, const float* __restrict__ W1,
    const float* __restrict__ b1, const float* __restrict__ W2,
    const float* __restrict__ b2, float* __restrict__ out) {
    __shared__ float2 sW[H * 32];
    __shared__ float sb[H];
    __shared__ float sW2[H];
    for (int idx = threadIdx.x; idx < H * 32; idx += 256) {
        int k = idx >> 5, j = idx & 31;
        sW[idx] = make_float2(W1[k * H + j], W1[k * H + j + 32]);
    }
    if (threadIdx.x < H) { sb[threadIdx.x] = b1[threadIdx.x]; sW2[threadIdx.x] = W2[threadIdx.x]; }
    __syncthreads();
    int warp = threadIdx.x >> 5, lane = threadIdx.x & 31;
    int gi = blockIdx.x * 8 + warp;
    const float* row = g + gi * H;
    float f0 = row[lane], f1 = row[lane + 32];
    float a0 = sb[lane], a1 = sb[lane + 32];
    #pragma unroll
    for (int k = 0; k < H; k++) {
        float fk = __shfl_sync(0xffffffffu, (k < 32 ? f0 : f1), k & 31);
        float2 w = sW[k * 32 + lane];
        a0 += fk * w.x; a1 += fk * w.y;
    }
    a0 = lrelu(a0); a1 = lrelu(a1);
    float p = a0 * sW2[lane] + a1 * sW2[lane + 32];
    #pragma unroll
    for (int o = 16; o; o >>= 1) p += __shfl_xor_sync(0xffffffffu, p, o);
    if (lane == 0) out[gi] = p + b2[0];
}

// ---------------- launch ----------------
extern "C" void kernel_launch(void* const* d_in, const int* in_sizes, int n_in,
                              void* d_out, int out_size) {
    const float* node_feats = (const float*)d_in[0];
    const float* edge_feats = (const float*)d_in[1];
    const int*   src        = (const int*)d_in[2];
    const int*   dst        = (const int*)d_in[3];
    const int*   gid        = (const int*)d_in[4];
    const float* Wn = (const float*)d_in[5];
    const float* bn = (const float*)d_in[6];
    const float* We = (const float*)d_in[7];
    const float* be = (const float*)d_in[8];
    const float* Wi = (const float*)d_in[9];
    const float* bi = (const float*)d_in[10];
    const float* Wa = (const float*)d_in[11];
    const float* ba = (const float*)d_in[12];
    const float* Wl = (const float*)d_in[13];
    const float* bl = (const float*)d_in[14];
    const float* W1 = (const float*)d_in[15];
    const float* b1 = (const float*)d_in[16];
    const float* W2 = (const float*)d_in[17];
    const float* b2 = (const float*)d_in[18];
    float* out = (float*)d_out;

    __half *p_node, *p_h0, *p_hA, *p_hB;
    float *p_aggA, *p_aggB, *p_gpool, *p_Wc, *p_bc;
    cudaGetSymbolAddress((void**)&p_node, g_node);
    cudaGetSymbolAddress((void**)&p_h0, g_h0);
    cudaGetSymbolAddress((void**)&p_hA, g_hA);
    cudaGetSymbolAddress((void**)&p_hB, g_hB);
    cudaGetSymbolAddress((void**)&p_aggA, g_aggA);
    cudaGetSymbolAddress((void**)&p_aggB, g_aggB);
    cudaGetSymbolAddress((void**)&p_gpool, g_gpool);
    cudaGetSymbolAddress((void**)&p_Wc, g_Wc);
    cudaGetSymbolAddress((void**)&p_bc, g_bc);

    const int SM_NP   = (WPB * NODE_DIM * ROWSTRIDE + NODE_DIM * 64 + H) * 4;
    const int SM_H0   = (WPB * K_H0 * ROWSTRIDE + K_H0 * 64 + H) * 4;
    const int SM_CONV = (WPB * H * ROWSTRIDE + H * 64 + H) * 4;
    const int SM_RO   = (WPB * H * ROWSTRIDE + 2 * H * 64 + H) * 4;
    cudaFuncSetAttribute(node_proj_kernel, cudaFuncAttributeMaxDynamicSharedMemorySize, SM_NP);
    cudaFuncSetAttribute(h0_kernel,       cudaFuncAttributeMaxDynamicSharedMemorySize, SM_H0);
    cudaFuncSetAttribute(conv_kernel,     cudaFuncAttributeMaxDynamicSharedMemorySize, SM_CONV);
    cudaFuncSetAttribute(readout_kernel,  cudaFuncAttributeMaxDynamicSharedMemorySize, SM_RO);

    const size_t aggBytes = (size_t)N_NODES * H * sizeof(float);
    const int EGRID = N_EDGES / (WPB * RPW);   // 12500
    const int NGRID = N_NODES / (WPB * RPW);   // 3125

    prep_kernel<<<4, 256>>>(We, be, Wi, bi, p_Wc, p_bc);
    node_proj_kernel<<<NGRID, 256, SM_NP>>>(node_feats, Wn, bn, p_node);

    cudaMemsetAsync(p_aggA, 0, aggBytes);
    h0_kernel<<<EGRID, 256, SM_H0>>>(p_node, edge_feats, src, dst, Wi, p_Wc, p_bc,
                                     p_h0, p_aggA);

    cudaMemsetAsync(p_aggB, 0, aggBytes);
    conv_kernel<<<EGRID, 256, SM_CONV>>>(Wl + 0 * H * H, bl + 0 * H, src, dst,
                                         p_aggA, p_h0, p_h0, p_hA, p_aggB);
    cudaMemsetAsync(p_aggA, 0, aggBytes);
    conv_kernel<<<EGRID, 256, SM_CONV>>>(Wl + 1 * H * H, bl + 1 * H, src, dst,
                                         p_aggB, p_hA, p_h0, p_hB, p_aggA);
    cudaMemsetAsync(p_aggB, 0, aggBytes);
    conv_kernel<<<EGRID, 256, SM_CONV>>>(Wl + 2 * H * H, bl + 2 * H, src, dst,
                                         p_aggA, p_hB, p_h0, p_hA, p_aggB);
    cudaMemsetAsync(p_aggA, 0, aggBytes);
    conv_kernel<<<EGRID, 256, SM_CONV>>>(Wl + 3 * H * H, bl + 3 * H, src, dst,
                                         p_aggB, p_hA, p_h0, p_hB, p_aggA);

    cudaMemsetAsync(p_gpool, 0, (size_t)N_GRAPHS * H * sizeof(float));
    readout_kernel<<<NGRID, 256, SM_RO>>>(p_node, p_aggA, Wa, ba, gid, p_gpool);
    head_kernel<<<N_GRAPHS / 8, 256>>>(p_gpool, W1, b1, W2, b2, out);
}

// round 4
// speedup vs baseline: 1.8636x; 1.1528x over previous
#include <cuda_runtime.h>
#include <cuda_fp16.h>

#define N_NODES 400000
#define N_EDGES 1600000
#define N_GRAPHS 10000
#define H 64
#define NODE_DIM 74
#define EDGE_DIM 13
#define WPB 8        // warps per block (FFMA kernels)
#define RPW 16       // rows per warp
#define ROWSTRIDE 20 // floats per k-row in sM staging (FFMA kernels)
#define CT 5         // edge-tiles (of 16) per warp in the MMA conv kernel

typedef unsigned long long ull;

// ---------------- device scratch ----------------
__device__ __half g_node[(size_t)N_NODES * H];
__device__ __half g_h0[(size_t)N_EDGES * H];
__device__ __half g_hA[(size_t)N_EDGES * H];
__device__ __half g_hB[(size_t)N_EDGES * H];
__device__ float g_aggA[(size_t)N_NODES * H];
__device__ float g_aggB[(size_t)N_NODES * H];
__device__ float g_gpool[(size_t)N_GRAPHS * H];
__device__ float g_Wc[EDGE_DIM * H];
__device__ float g_bc[H];

__device__ __forceinline__ float lrelu(float v) { return fmaxf(v, 0.01f * v); }

__device__ __forceinline__ ull pack2(float x, float y) {
    ull r; asm("mov.b64 %0, {%1, %2};" : "=l"(r) : "f"(x), "f"(y)); return r;
}
__device__ __forceinline__ float2 unpack2(ull v) {
    float2 r; asm("mov.b64 {%0, %1}, %2;" : "=f"(r.x), "=f"(r.y) : "l"(v)); return r;
}
#define FFMA2(acc, a, b) asm("fma.rn.f32x2 %0, %1, %2, %0;" : "+l"(acc) : "l"(a), "l"(b))

#define KSTEP(q0, q1, q2, q3, wx, wy, A, B)                                   \
    FFMA2(A[0], q0.x, wx); FFMA2(A[1], q0.y, wx);                             \
    FFMA2(A[2], q1.x, wx); FFMA2(A[3], q1.y, wx);                             \
    FFMA2(A[4], q2.x, wx); FFMA2(A[5], q2.y, wx);                             \
    FFMA2(A[6], q3.x, wx); FFMA2(A[7], q3.y, wx);                             \
    FFMA2(B[0], q0.x, wy); FFMA2(B[1], q0.y, wy);                             \
    FFMA2(B[2], q1.x, wy); FFMA2(B[3], q1.y, wy);                             \
    FFMA2(B[4], q2.x, wy); FFMA2(B[5], q2.y, wy);                             \
    FFMA2(B[6], q3.x, wy); FFMA2(B[7], q3.y, wy)

// ---------------- prep: fold edge projection through Wi ----------------
__global__ void prep_kernel(const float* __restrict__ We, const float* __restrict__ be,
                            const float* __restrict__ Wi, const float* __restrict__ bi,
                            float* __restrict__ Wc, float* __restrict__ bc) {
    int tid = blockIdx.x * blockDim.x + threadIdx.x;
    if (tid < EDGE_DIM * H) {
        int d = tid >> 6, j = tid & 63;
        float s = 0.f;
        #pragma unroll 8
        for (int k = 0; k < H; k++) s += We[d * H + k] * Wi[(H + k) * H + j];
        Wc[tid] = s;
    }
    if (tid < H) {
        float s = bi[tid];
        #pragma unroll 8
        for (int k = 0; k < H; k++) s += be[k] * Wi[(H + k) * H + tid];
        bc[tid] = s;
    }
}

// ---------------- node projection (K=74), fp16 output ----------------
__global__ __launch_bounds__(256) void node_proj_kernel(
    const float* __restrict__ nf, const float* __restrict__ Wn,
    const float* __restrict__ bn, __half* __restrict__ node) {
    extern __shared__ __align__(16) float dsm[];
    float* sM = dsm;
    float2* sW = (float2*)(dsm + WPB * NODE_DIM * ROWSTRIDE);
    float* sb = (float*)(sW + NODE_DIM * 32);
    for (int idx = threadIdx.x; idx < NODE_DIM * 32; idx += 256) {
        int k = idx >> 5, j = idx & 31;
        sW[idx] = make_float2(Wn[k * H + j], Wn[k * H + j + 32]);
    }
    if (threadIdx.x < H) sb[threadIdx.x] = bn[threadIdx.x];
    __syncthreads();
    int warp = threadIdx.x >> 5, lane = threadIdx.x & 31;
    int nb = (blockIdx.x * WPB + warp) * RPW;
    float* myM = sM + warp * NODE_DIM * ROWSTRIDE;

    float4 b0, b1, b2;
    #pragma unroll
    for (int c = 0; c < 4; c++) {
        #pragma unroll
        for (int t = 0; t < 4; t++) {
            int n = nb + c * 4 + t;
            const float* row = nf + (size_t)n * NODE_DIM;
            ((float*)&b0)[t] = row[lane];
            ((float*)&b1)[t] = row[lane + 32];
            ((float*)&b2)[t] = (lane < NODE_DIM - 64) ? row[lane + 64] : 0.f;
        }
        *(float4*)(myM + (lane * 5 + c) * 4) = b0;
        *(float4*)(myM + ((lane + 32) * 5 + c) * 4) = b1;
        if (lane < NODE_DIM - 64) *(float4*)(myM + ((lane + 64) * 5 + c) * 4) = b2;
    }
    __syncwarp();

    float bj0 = sb[lane], bj1 = sb[lane + 32];
    ull A[8], B[8];
    #pragma unroll
    for (int p = 0; p < 8; p++) { A[p] = pack2(bj0, bj0); B[p] = pack2(bj1, bj1); }
    #pragma unroll 2
    for (int k = 0; k < NODE_DIM; k++) {
        const ulonglong2* row = (const ulonglong2*)(myM + k * ROWSTRIDE);
        ulonglong2 q0 = row[0], q1 = row[1], q2 = row[2], q3 = row[3];
        float2 w = sW[k * 32 + lane];
        ull wx = pack2(w.x, w.x), wy = pack2(w.y, w.y);
        KSTEP(q0, q1, q2, q3, wx, wy, A, B);
    }
    #pragma unroll
    for (int p = 0; p < 8; p++) {
        float2 vA = unpack2(A[p]), vB = unpack2(B[p]);
        int n0 = nb + 2 * p, n1 = n0 + 1;
        node[n0 * H + lane]      = __float2half_rn(vA.x);
        node[n0 * H + lane + 32] = __float2half_rn(vB.x);
        node[n1 * H + lane]      = __float2half_rn(vA.y);
        node[n1 * H + lane + 32] = __float2half_rn(vB.y);
    }
}

// ---------------- h0 (K=77): lrelu(node[src]@Wi_top + ef@Wc + bc), scatter ----------------
#define K_H0 (H + EDGE_DIM)
__global__ __launch_bounds__(256) void h0_kernel(
    const __half* __restrict__ node, const float* __restrict__ ef,
    const int* __restrict__ src, const int* __restrict__ dst,
    const float* __restrict__ Wi, const float* __restrict__ Wc,
    const float* __restrict__ bc, __half* __restrict__ h0,
    float* __restrict__ agg_out) {
    extern __shared__ __align__(16) float dsm[];
    float* sM = dsm;
    float2* sW = (float2*)(dsm + WPB * K_H0 * ROWSTRIDE);
    float* sb = (float*)(sW + K_H0 * 32);
    for (int idx = threadIdx.x; idx < K_H0 * 32; idx += 256) {
        int k = idx >> 5, j = idx & 31;
        float wx, wy;
        if (k < H) { wx = Wi[k * H + j]; wy = Wi[k * H + j + 32]; }
        else       { wx = Wc[(k - H) * H + j]; wy = Wc[(k - H) * H + j + 32]; }
        sW[idx] = make_float2(wx, wy);
    }
    if (threadIdx.x < H) sb[threadIdx.x] = bc[threadIdx.x];
    __syncthreads();
    int warp = threadIdx.x >> 5, lane = threadIdx.x & 31;
    int eb = (blockIdx.x * WPB + warp) * RPW;
    float* myM = sM + warp * K_H0 * ROWSTRIDE;
    int sidx = src[eb + (lane & 15)];
    int didx = dst[eb + (lane & 15)];

    float4 b0, b1, b2;
    #pragma unroll
    for (int c = 0; c < 4; c++) {
        #pragma unroll
        for (int t = 0; t < 4; t++) {
            int i = c * 4 + t;
            int s = __shfl_sync(0xffffffffu, sidx, i);
            int e = eb + i;
            ((float*)&b0)[t] = __half2float(node[s * H + lane]);
            ((float*)&b1)[t] = __half2float(node[s * H + lane + 32]);
            ((float*)&b2)[t] = (lane < EDGE_DIM) ? ef[e * EDGE_DIM + lane] : 0.f;
        }
        *(float4*)(myM + (lane * 5 + c) * 4) = b0;
        *(float4*)(myM + ((lane + 32) * 5 + c) * 4) = b1;
        if (lane < EDGE_DIM) *(float4*)(myM + ((lane + 64) * 5 + c) * 4) = b2;
    }
    __syncwarp();

    float bj0 = sb[lane], bj1 = sb[lane + 32];
    ull A[8], B[8];
    #pragma unroll
    for (int p = 0; p < 8; p++) { A[p] = pack2(bj0, bj0); B[p] = pack2(bj1, bj1); }
    #pragma unroll 7
    for (int k = 0; k < K_H0; k++) {
        const ulonglong2* row = (const ulonglong2*)(myM + k * ROWSTRIDE);
        ulonglong2 q0 = row[0], q1 = row[1], q2 = row[2], q3 = row[3];
        float2 w = sW[k * 32 + lane];
        ull wx = pack2(w.x, w.x), wy = pack2(w.y, w.y);
        KSTEP(q0, q1, q2, q3, wx, wy, A, B);
    }
    #pragma unroll
    for (int p = 0; p < 8; p++) {
        float2 vA = unpack2(A[p]), vB = unpack2(B[p]);
        int e0 = eb + 2 * p, e1 = e0 + 1;
        int d0 = __shfl_sync(0xffffffffu, didx, 2 * p);
        int d1 = __shfl_sync(0xffffffffu, didx, 2 * p + 1);
        float o00 = lrelu(vA.x), o01 = lrelu(vB.x);
        float o10 = lrelu(vA.y), o11 = lrelu(vB.y);
        h0[e0 * H + lane]      = __float2half_rn(o00);
        h0[e0 * H + lane + 32] = __float2half_rn(o01);
        h0[e1 * H + lane]      = __float2half_rn(o10);
        h0[e1 * H + lane + 32] = __float2half_rn(o11);
        atomicAdd(&agg_out[d0 * H + lane], o00);
        atomicAdd(&agg_out[d0 * H + lane + 32], o01);
        atomicAdd(&agg_out[d1 * H + lane], o10);
        atomicAdd(&agg_out[d1 * H + lane + 32], o11);
    }
}

// ---------------- conv layer via tensor cores (HMMA m16n8k16) ----------------
// h_out[e] = lrelu(h0[e] + (agg_in[src[e]] - h_in[e^1]) @ W + b); scatter into agg_out
__global__ __launch_bounds__(256) void conv_mma_kernel(
    const float* __restrict__ W, const float* __restrict__ bias,
    const int* __restrict__ src, const int* __restrict__ dst,
    const float* __restrict__ agg_in, const __half* __restrict__ h_in,
    const __half* __restrict__ h0, __half* __restrict__ h_out,
    float* __restrict__ agg_out) {
    __shared__ __align__(16) __half sW[64 * 72];       // W fp16, row-major, ld=72 (conflict-free)
    __shared__ __align__(16) __half sT[8][16 * 72];    // per-warp 16x64 staging, ld=72

    int tid = threadIdx.x;
    for (int idx = tid; idx < 64 * 64; idx += 256) {
        int k = idx >> 6, n = idx & 63;
        sW[k * 72 + n] = __float2half_rn(W[idx]);
    }
    __syncthreads();
    int warp = tid >> 5, lane = tid & 31;
    float2 bias2 = *(const float2*)&bias[2 * lane];

    // --- load W as mma B-fragments (once per warp): bfr[ntile][ktile][2] ---
    unsigned bfr[8][4][2];
    #pragma unroll
    for (int nt = 0; nt < 8; nt++) {
        #pragma unroll
        for (int kh = 0; kh < 2; kh++) {
            unsigned r0, r1, r2, r3;
            unsigned addr = (unsigned)__cvta_generic_to_shared(&sW[(kh * 32 + lane) * 72 + nt * 8]);
            asm volatile("ldmatrix.sync.aligned.m8n8.x4.trans.shared.b16 {%0,%1,%2,%3}, [%4];"
                         : "=r"(r0), "=r"(r1), "=r"(r2), "=r"(r3) : "r"(addr));
            bfr[nt][kh * 2][0] = r0;     bfr[nt][kh * 2][1] = r1;
            bfr[nt][kh * 2 + 1][0] = r2; bfr[nt][kh * 2 + 1][1] = r3;
        }
    }

    __half* myT = sT[warp];
    int base = ((blockIdx.x * 8 + warp) * CT) * 16;
    // precompute ldmatrix-A address pieces
    int am = lane >> 3;
    int arow = (am & 1) * 8 + (lane & 7);
    int acol0 = (am >> 1) * 8;

    for (int t = 0; t < CT; t++) {
        int eb = base + t * 16;
        int sidx = src[eb + (lane & 15)];
        int didx = dst[eb + (lane & 15)];
        // --- gather m = agg[src] - h[rev], stage as fp16 ---
        #pragma unroll
        for (int i = 0; i < 16; i++) {
            int s = __shfl_sync(0xffffffffu, sidx, i);
            int r = (eb + i) ^ 1;
            float2 a = *(const float2*)&agg_in[s * 64 + 2 * lane];
            float2 hf = __half22float2(*(const __half2*)&h_in[r * 64 + 2 * lane]);
            *(__half2*)&myT[i * 72 + 2 * lane] = __floats2half2_rn(a.x - hf.x, a.y - hf.y);
        }
        __syncwarp();
        // --- GEMM: [16x64] @ [64x64] via 4 ktiles x 8 ntiles ---
        float acc[8][4];
        #pragma unroll
        for (int nt = 0; nt < 8; nt++) {
            acc[nt][0] = 0.f; acc[nt][1] = 0.f; acc[nt][2] = 0.f; acc[nt][3] = 0.f;
        }
        #pragma unroll
        for (int kt = 0; kt < 4; kt++) {
            unsigned a0, a1, a2, a3;
            unsigned addr = (unsigned)__cvta_generic_to_shared(&myT[arow * 72 + kt * 16 + acol0]);
            asm volatile("ldmatrix.sync.aligned.m8n8.x4.shared.b16 {%0,%1,%2,%3}, [%4];"
                         : "=r"(a0), "=r"(a1), "=r"(a2), "=r"(a3) : "r"(addr));
            #pragma unroll
            for (int nt = 0; nt < 8; nt++) {
                asm volatile("mma.sync.aligned.m16n8k16.row.col.f32.f16.f16.f32 "
                             "{%0,%1,%2,%3}, {%4,%5,%6,%7}, {%8,%9}, {%0,%1,%2,%3};"
                             : "+f"(acc[nt][0]), "+f"(acc[nt][1]), "+f"(acc[nt][2]), "+f"(acc[nt][3])
                             : "r"(a0), "r"(a1), "r"(a2), "r"(a3),
                               "r"(bfr[nt][kt][0]), "r"(bfr[nt][kt][1]));
            }
        }
        __syncwarp();
        // --- transpose acc fragments through smem (half2), conflict-free ---
        int qrow = lane >> 2, qc = (lane & 3) * 2;
        #pragma unroll
        for (int nt = 0; nt < 8; nt++) {
            *(__half2*)&myT[qrow * 72 + nt * 8 + qc]       = __floats2half2_rn(acc[nt][0], acc[nt][1]);
            *(__half2*)&myT[(qrow + 8) * 72 + nt * 8 + qc] = __floats2half2_rn(acc[nt][2], acc[nt][3]);
        }
        __syncwarp();
        // --- coalesced epilogue: bias + h0 + lrelu, store h_out, scatter agg ---
        #pragma unroll
        for (int i = 0; i < 16; i++) {
            int d = __shfl_sync(0xffffffffu, didx, i);
            float2 m2  = __half22float2(*(const __half2*)&myT[i * 72 + 2 * lane]);
            float2 h0f = __half22float2(*(const __half2*)&h0[(eb + i) * 64 + 2 * lane]);
            float o0 = lrelu(h0f.x + bias2.x + m2.x);
            float o1 = lrelu(h0f.y + bias2.y + m2.y);
            *(__half2*)&h_out[(eb + i) * 64 + 2 * lane] = __floats2half2_rn(o0, o1);
            asm volatile("red.global.add.v2.f32 [%0], {%1, %2};"
                         :: "l"(&agg_out[d * 64 + 2 * lane]), "f"(o0), "f"(o1) : "memory");
        }
        __syncwarp();
    }
}

// ---------------- node readout + graph pooling (K=128, two stages) ----------------
__global__ __launch_bounds__(256) void readout_kernel(
    const __half* __restrict__ node, const float* __restrict__ agg,
    const float* __restrict__ Wa, const float* __restrict__ ba,
    const int* __restrict__ gid, float* __restrict__ gpool) {
    extern __shared__ __align__(16) float dsm[];
    float* sM = dsm;
    float2* sW = (float2*)(dsm + WPB * H * ROWSTRIDE);
    float* sb = (float*)(sW + 2 * H * 32);
    for (int idx = threadIdx.x; idx < 2 * H * 32; idx += 256) {
        int k = idx >> 5, j = idx & 31;
        sW[idx] = make_float2(Wa[k * H + j], Wa[k * H + j + 32]);
    }
    if (threadIdx.x < H) sb[threadIdx.x] = ba[threadIdx.x];
    __syncthreads();
    int warp = threadIdx.x >> 5, lane = threadIdx.x & 31;
    int nb = (blockIdx.x * WPB + warp) * RPW;
    float* myM = sM + warp * H * ROWSTRIDE;
    int gidx = gid[nb + (lane & 15)];

    float bj0 = sb[lane], bj1 = sb[lane + 32];
    ull A[8], B[8];
    #pragma unroll
    for (int p = 0; p < 8; p++) { A[p] = pack2(bj0, bj0); B[p] = pack2(bj1, bj1); }

    #pragma unroll
    for (int stage = 0; stage < 2; stage++) {
        float4 b0, b1;
        #pragma unroll
        for (int c = 0; c < 4; c++) {
            #pragma unroll
            for (int t = 0; t < 4; t++) {
                int n = nb + c * 4 + t;
                if (stage == 0) {
                    ((float*)&b0)[t] = __half2float(node[n * H + lane]);
                    ((float*)&b1)[t] = __half2float(node[n * H + lane + 32]);
                } else {
                    ((float*)&b0)[t] = agg[n * H + lane];
                    ((float*)&b1)[t] = agg[n * H + lane + 32];
                }
            }
            *(float4*)(myM + (lane * 5 + c) * 4) = b0;
            *(float4*)(myM + ((lane + 32) * 5 + c) * 4) = b1;
        }
        __syncwarp();
        #pragma unroll 8
        for (int k = 0; k < H; k++) {
            const ulonglong2* row = (const ulonglong2*)(myM + k * ROWSTRIDE);
            ulonglong2 q0 = row[0], q1 = row[1], q2 = row[2], q3 = row[3];
            float2 w = sW[(stage * H + k) * 32 + lane];
            ull wx = pack2(w.x, w.x), wy = pack2(w.y, w.y);
            KSTEP(q0, q1, q2, q3, wx, wy, A, B);
        }
        __syncwarp();
    }
    #pragma unroll
    for (int p = 0; p < 8; p++) {
        float2 vA = unpack2(A[p]), vB = unpack2(B[p]);
        int g0 = __shfl_sync(0xffffffffu, gidx, 2 * p);
        int g1 = __shfl_sync(0xffffffffu, gidx, 2 * p + 1);
        atomicAdd(&gpool[g0 * H + lane], lrelu(vA.x));
        atomicAdd(&gpool[g0 * H + lane + 32], lrelu(vB.x));
        atomicAdd(&gpool[g1 * H + lane], lrelu(vA.y));
        atomicAdd(&gpool[g1 * H + lane + 32], lrelu(vB.y));
    }
}

// ---------------- head ----------------
__global__ __launch_bounds__(256) void head_kernel(
    const float* __restrict__ g, const float* __restrict__ W1,
    const float* __restrict__ b1, const float* __restrict__ W2,
    const float* __restrict__ b2, float* __restrict__ out) {
    __shared__ float2 sW[H * 32];
    __shared__ float sb[H];
    __shared__ float sW2[H];
    for (int idx = threadIdx.x; idx < H * 32; idx += 256) {
        int k = idx >> 5, j = idx & 31;
        sW[idx] = make_float2(W1[k * H + j], W1[k * H + j + 32]);
    }
    if (threadIdx.x < H) { sb[threadIdx.x] = b1[threadIdx.x]; sW2[threadIdx.x] = W2[threadIdx.x]; }
    __syncthreads();
    int warp = threadIdx.x >> 5, lane = threadIdx.x & 31;
    int gi = blockIdx.x * 8 + warp;
    const float* row = g + gi * H;
    float f0 = row[lane], f1 = row[lane + 32];
    float a0 = sb[lane], a1 = sb[lane + 32];
    #pragma unroll
    for (int k = 0; k < H; k++) {
        float fk = __shfl_sync(0xffffffffu, (k < 32 ? f0 : f1), k & 31);
        float2 w = sW[k * 32 + lane];
        a0 += fk * w.x; a1 += fk * w.y;
    }
    a0 = lrelu(a0); a1 = lrelu(a1);
    float p = a0 * sW2[lane] + a1 * sW2[lane + 32];
    #pragma unroll
    for (int o = 16; o; o >>= 1) p += __shfl_xor_sync(0xffffffffu, p, o);
    if (lane == 0) out[gi] = p + b2[0];
}

// ---------------- launch ----------------
extern "C" void kernel_launch(void* const* d_in, const int* in_sizes, int n_in,
                              void* d_out, int out_size) {
    const float* node_feats = (const float*)d_in[0];
    const float* edge_feats = (const float*)d_in[1];
    const int*   src        = (const int*)d_in[2];
    const int*   dst        = (const int*)d_in[3];
    const int*   gid        = (const int*)d_in[4];
    const float* Wn = (const float*)d_in[5];
    const float* bn = (const float*)d_in[6];
    const float* We = (const float*)d_in[7];
    const float* be = (const float*)d_in[8];
    const float* Wi = (const float*)d_in[9];
    const float* bi = (const float*)d_in[10];
    const float* Wa = (const float*)d_in[11];
    const float* ba = (const float*)d_in[12];
    const float* Wl = (const float*)d_in[13];
    const float* bl = (const float*)d_in[14];
    const float* W1 = (const float*)d_in[15];
    const float* b1 = (const float*)d_in[16];
    const float* W2 = (const float*)d_in[17];
    const float* b2 = (const float*)d_in[18];
    float* out = (float*)d_out;

    __half *p_node, *p_h0, *p_hA, *p_hB;
    float *p_aggA, *p_aggB, *p_gpool, *p_Wc, *p_bc;
    cudaGetSymbolAddress((void**)&p_node, g_node);
    cudaGetSymbolAddress((void**)&p_h0, g_h0);
    cudaGetSymbolAddress((void**)&p_hA, g_hA);
    cudaGetSymbolAddress((void**)&p_hB, g_hB);
    cudaGetSymbolAddress((void**)&p_aggA, g_aggA);
    cudaGetSymbolAddress((void**)&p_aggB, g_aggB);
    cudaGetSymbolAddress((void**)&p_gpool, g_gpool);
    cudaGetSymbolAddress((void**)&p_Wc, g_Wc);
    cudaGetSymbolAddress((void**)&p_bc, g_bc);

    const int SM_NP = (WPB * NODE_DIM * ROWSTRIDE + NODE_DIM * 64 + H) * 4;
    const int SM_H0 = (WPB * K_H0 * ROWSTRIDE + K_H0 * 64 + H) * 4;
    const int SM_RO = (WPB * H * ROWSTRIDE + 2 * H * 64 + H) * 4;
    cudaFuncSetAttribute(node_proj_kernel, cudaFuncAttributeMaxDynamicSharedMemorySize, SM_NP);
    cudaFuncSetAttribute(h0_kernel,      cudaFuncAttributeMaxDynamicSharedMemorySize, SM_H0);
    cudaFuncSetAttribute(readout_kernel, cudaFuncAttributeMaxDynamicSharedMemorySize, SM_RO);

    const size_t aggBytes = (size_t)N_NODES * H * sizeof(float);
    const int EGRID  = N_EDGES / (WPB * RPW);        // 12500 (h0)
    const int NGRID  = N_NODES / (WPB * RPW);        // 3125
    const int CGRID  = N_EDGES / (8 * CT * 16);      // 2500 (conv mma)

    prep_kernel<<<4, 256>>>(We, be, Wi, bi, p_Wc, p_bc);
    node_proj_kernel<<<NGRID, 256, SM_NP>>>(node_feats, Wn, bn, p_node);

    cudaMemsetAsync(p_aggA, 0, aggBytes);
    h0_kernel<<<EGRID, 256, SM_H0>>>(p_node, edge_feats, src, dst, Wi, p_Wc, p_bc,
                                     p_h0, p_aggA);

    cudaMemsetAsync(p_aggB, 0, aggBytes);
    conv_mma_kernel<<<CGRID, 256>>>(Wl + 0 * H * H, bl + 0 * H, src, dst,
                                    p_aggA, p_h0, p_h0, p_hA, p_aggB);
    cudaMemsetAsync(p_aggA, 0, aggBytes);
    conv_mma_kernel<<<CGRID, 256>>>(Wl + 1 * H * H, bl + 1 * H, src, dst,
                                    p_aggB, p_hA, p_h0, p_hB, p_aggA);
    cudaMemsetAsync(p_aggB, 0, aggBytes);
    conv_mma_kernel<<<CGRID, 256>>>(Wl + 2 * H * H, bl + 2 * H, src, dst,
                                    p_aggA, p_hB, p_h0, p_hA, p_aggB);
    cudaMemsetAsync(p_aggA, 0, aggBytes);
    conv_mma_kernel<<<CGRID, 256>>>(Wl + 3 * H * H, bl + 3 * H, src, dst,
                                    p_aggB, p_hA, p_h0, p_hB, p_aggA);

    cudaMemsetAsync(p_gpool, 0, (size_t)N_GRAPHS * H * sizeof(float));
    readout_kernel<<<NGRID, 256, SM_RO>>>(p_node, p_aggA, Wa, ba, gid, p_gpool);
    head_kernel<<<N_GRAPHS / 8, 256>>>(p_gpool, W1, b1, W2, b2, out);
}